// round 13
// baseline (speedup 1.0000x reference)
#include <cuda_runtime.h>
#include <cuda_fp16.h>
#include <cstdint>

// ---------------------------------------------------------------------------
// ChannelProjection via mma.sync (HMMA fp16, base-target ISA).
// R12: single-read-per-channel. GEMM1 C-frags ARE GEMM2 A-frags (register
// chain, no S smem round-trip). Residuals reconstructed on-chip:
//   z1 residuals  = (A_hi + A_lo) * sigma + mu   (fp32-exact, 2^-22)
//   z2 residuals  = raw z2 tile staged via cp.async under the GEMM chain.
// Main-kernel DRAM traffic: 906 -> 604 MB. 107KB smem, 2 CTAs/SM.
// ---------------------------------------------------------------------------

#define C_TOT   128
#define CC      64
#define HW      36864
#define NSAMP   16
#define CHW     (C_TOT * HW)
#define NPIX    (NSAMP * HW)
#define RED_BLOCKS  64
#define RED_THREADS 256

#define TPB       4                       // 128-px tiles per block
#define BLOCKS_PER_SAMPLE 72              // 72 * 4 * 128 = 36864 px
#define MAIN_GRID (NSAMP * BLOCKS_PER_SAMPLE)   // 1152
#define Z2STR 132                         // fp32 row stride of z2/stg tile

// smem offsets; A/W1 rows 144B (72 fp16), W2 rows 272B (136 fp16)
#define OFF_W1    0          // [128h][72k]    18432
#define OFF_W2    18432      // [64o][136h]    17408
#define OFF_AHI   35840      // [128px][72k]   18432
#define OFF_ALO   54272      //                18432
#define OFF_Z2    72704      // [64c][132] f32 33792 (z1-raw stg aliases, then z2)
#define OFF_B1    106496     // 128 f32
#define OFF_B2    107008     // 64 f32
#define SMEM_MAIN 107264

__device__ float g_psum[NSAMP * RED_BLOCKS];
__device__ float g_psq [NSAMP * RED_BLOCKS];
__device__ float g_mu  [NSAMP];
__device__ float g_rs  [NSAMP];
__device__ float g_sg  [NSAMP];
__device__ uint4 g_w1h[1152];   // 128*72 fp16
__device__ uint4 g_w2h[1088];   // 64*136 fp16

// ---------------- helpers ---------------------------------------------------
__device__ __forceinline__ uint32_t smem_u32(const void* p) {
    uint32_t a;
    asm("{ .reg .u64 t; cvta.to.shared.u64 t, %1; cvt.u32.u64 %0, t; }"
        : "=r"(a) : "l"(p));
    return a;
}
__device__ __forceinline__ void ldsm_x4(uint32_t (&r)[4], uint32_t addr) {
    asm volatile("ldmatrix.sync.aligned.m8n8.x4.shared.b16 {%0,%1,%2,%3}, [%4];"
                 : "=r"(r[0]), "=r"(r[1]), "=r"(r[2]), "=r"(r[3]) : "r"(addr));
}
__device__ __forceinline__ void ldsm_x2(uint32_t& r0, uint32_t& r1, uint32_t addr) {
    asm volatile("ldmatrix.sync.aligned.m8n8.x2.shared.b16 {%0,%1}, [%2];"
                 : "=r"(r0), "=r"(r1) : "r"(addr));
}
__device__ __forceinline__ void mma_f16(float (&c)[4], const uint32_t (&a)[4],
                                        uint32_t b0, uint32_t b1) {
    asm volatile(
        "mma.sync.aligned.m16n8k16.row.col.f32.f16.f16.f32 "
        "{%0,%1,%2,%3}, {%4,%5,%6,%7}, {%8,%9}, {%0,%1,%2,%3};"
        : "+f"(c[0]), "+f"(c[1]), "+f"(c[2]), "+f"(c[3])
        : "r"(a[0]), "r"(a[1]), "r"(a[2]), "r"(a[3]), "r"(b0), "r"(b1));
}
__device__ __forceinline__ uint32_t packh(__half a, __half b) {
    __half2 h; h.x = a; h.y = b;
    return *(uint32_t*)&h;
}
__device__ __forceinline__ void split2h(float v0, float v1, uint32_t& hi, uint32_t& lo) {
    const __half h0 = __float2half_rn(v0);
    const __half h1 = __float2half_rn(v1);
    const __half l0 = __float2half_rn(v0 - __half2float(h0));
    const __half l1 = __float2half_rn(v1 - __half2float(h1));
    hi = packh(h0, h1);
    lo = packh(l0, l1);
}
__device__ __forceinline__ float silu_f(float h) {
    return __fdividef(h, 1.f + __expf(-h));
}
__device__ __forceinline__ void cpasync16(uint32_t dst, const void* src) {
    asm volatile("cp.async.cg.shared.global [%0], [%1], 16;" :: "r"(dst), "l"(src));
}
#define CP_COMMIT() asm volatile("cp.async.commit_group;" ::: "memory")
#define CP_WAIT0()  asm volatile("cp.async.wait_group 0;" ::: "memory")

// ---------------- stage 1: per-sample partial sums --------------------------
__global__ void cp_stats_kernel(const float* __restrict__ z0) {
    const int b = blockIdx.y;
    const float4* z4 = (const float4*)(z0 + (size_t)b * CHW);
    const int n4 = CHW / 4;
    float s = 0.f, q = 0.f;
    for (int i = blockIdx.x * RED_THREADS + threadIdx.x; i < n4;
         i += RED_BLOCKS * RED_THREADS) {
        float4 v = z4[i];
        s += (v.x + v.y) + (v.z + v.w);
        q += (v.x * v.x + v.y * v.y) + (v.z * v.z + v.w * v.w);
    }
    #pragma unroll
    for (int off = 16; off; off >>= 1) {
        s += __shfl_down_sync(0xffffffffu, s, off);
        q += __shfl_down_sync(0xffffffffu, q, off);
    }
    __shared__ float ss[RED_THREADS / 32], sq[RED_THREADS / 32];
    const int w = threadIdx.x >> 5;
    if ((threadIdx.x & 31) == 0) { ss[w] = s; sq[w] = q; }
    __syncthreads();
    if (threadIdx.x == 0) {
        float S = 0.f, Q = 0.f;
        #pragma unroll
        for (int i = 0; i < RED_THREADS / 32; i++) { S += ss[i]; Q += sq[i]; }
        g_psum[b * RED_BLOCKS + blockIdx.x] = S;
        g_psq [b * RED_BLOCKS + blockIdx.x] = Q;
    }
}

// ---------------- stage 2: finalize + fp16 weights --------------------------
__global__ void cp_finalize_kernel(const float* __restrict__ w1,
                                   const float* __restrict__ w2) {
    const int t = threadIdx.x;   // 256
    if (t < NSAMP) {
        float S = 0.f, Q = 0.f;
        for (int i = 0; i < RED_BLOCKS; i++) {
            S += g_psum[t * RED_BLOCKS + i];
            Q += g_psq [t * RED_BLOCKS + i];
        }
        const float inv_n = 1.f / (float)CHW;
        const float mu  = S * inv_n;
        const float var = Q * inv_n - mu * mu;
        g_mu[t] = mu;
        g_rs[t] = rsqrtf(var + 1e-5f);
        g_sg[t] = sqrtf(var + 1e-5f);
    }
    __half* w1h = (__half*)g_w1h;
    __half* w2h = (__half*)g_w2h;
    for (int i = t; i < 128 * 64; i += 256) {      // w1[h][k] -> [h][72]
        const int h = i >> 6, k = i & 63;
        w1h[h * 72 + k] = __float2half_rn(w1[h * 64 + k]);
    }
    for (int i = t; i < 64 * 128; i += 256) {      // w2[o][h] -> [o][136]
        const int o = i >> 7, h = i & 127;
        w2h[o * 136 + h] = __float2half_rn(w2[o * 128 + h]);
    }
}

// ---------------- stage 3: HMMA main kernel (2 CTAs/SM) ---------------------
__global__ void __launch_bounds__(256, 2)
cp_main_kernel(const float* __restrict__ z0,
               const float* __restrict__ b1,
               const float* __restrict__ b2,
               float* __restrict__ out) {
    extern __shared__ char smc[];
    const uint32_t sb = smem_u32(smc);
    const int tid = threadIdx.x;
    const int w = tid >> 5, lane = tid & 31;
    const int g = lane >> 2, tig = lane & 3;
    const int lrow = lane & 15, lk = lane >> 4;          // ldsm.x4 mapping
    const int brow = lane & 7,  bk = (lane >> 3) & 1;    // ldsm.x2 mapping

    // ---- stage weights + biases ----
    for (int i = tid; i < 1152; i += 256) ((uint4*)(smc + OFF_W1))[i] = g_w1h[i];
    for (int i = tid; i < 1088; i += 256) ((uint4*)(smc + OFF_W2))[i] = g_w2h[i];
    float* b1s = (float*)(smc + OFF_B1);
    float* b2s = (float*)(smc + OFF_B2);
    if (tid < 128) b1s[tid] = b1[tid];
    if (tid < 64)  b2s[tid] = b2[tid];

    const int b = blockIdx.x / BLOCKS_PER_SAMPLE;
    const float* zb = z0 + (size_t)b * CHW;
    float*       ob = out + (size_t)b * CHW;
    const int p_base = (blockIdx.x % BLOCKS_PER_SAMPLE) * (TPB * 128);
    const float mu = g_mu[b];
    const float rs = g_rs[b];
    const float sg = g_sg[b];
    float* z2s = (float*)(smc + OFF_Z2);     // raw tile region (z1 then z2)

    for (int tl = 0; tl < TPB; tl++) {
        const int p0 = p_base + tl * 128;
        __syncthreads();   // prev epilogue's z2s/A reads done

        // ---- phase 1: raw z1 -> z2s region (8 LDG.128 / thread) ----
        #pragma unroll
        for (int k = 0; k < 8; k++) {
            const int i = tid + k * 256;          // 64ch x 32 float4
            const int c = i >> 5, f = (i & 31) * 4;
            *(float4*)(z2s + c * Z2STR + f) = *(const float4*)(zb + (size_t)c * HW + p0 + f);
        }
        __syncthreads();

        // ---- phase 2: normalize + split -> A hi/lo fp16 [px][72] ----
        #pragma unroll
        for (int k = 0; k < 4; k++) {
            const int i = tid + k * 256;          // 128px x 8 c-groups
            const int px = i & 127, c0 = (i >> 7) * 8;
            uint32_t hiw[4], low[4];
            #pragma unroll
            for (int j = 0; j < 4; j++) {
                const float v0 = (z2s[(c0 + 2 * j)     * Z2STR + px] - mu) * rs;
                const float v1 = (z2s[(c0 + 2 * j + 1) * Z2STR + px] - mu) * rs;
                split2h(v0, v1, hiw[j], low[j]);
            }
            *(uint4*)(smc + OFF_AHI + px * 144 + c0 * 2) = make_uint4(hiw[0], hiw[1], hiw[2], hiw[3]);
            *(uint4*)(smc + OFF_ALO + px * 144 + c0 * 2) = make_uint4(low[0], low[1], low[2], low[3]);
        }
        __syncthreads();   // A ready; z1 raw consumed

        // ---- phase 3: cp.async raw z2 -> z2s (lands under the GEMM chain) --
        #pragma unroll
        for (int k = 0; k < 8; k++) {
            const int i = tid + k * 256;          // 64ch x 32 float4
            const int c = i >> 5, f = (i & 31) * 4;
            cpasync16(sb + OFF_Z2 + (c * Z2STR + f) * 4,
                      zb + (size_t)(CC + c) * HW + p0 + f);
        }
        CP_COMMIT();

        // ---- GEMM1: [16px x 128h] per warp, K=64, 2 split passes ----
        float acc[16][4];
        #pragma unroll
        for (int nt = 0; nt < 16; nt++)
            #pragma unroll
            for (int i = 0; i < 4; i++) acc[nt][i] = 0.f;
        #pragma unroll
        for (int ks = 0; ks < 4; ks++) {
            uint32_t aH[4], aL[4];
            const uint32_t ad = sb + OFF_AHI + (w * 16 + lrow) * 144 + (ks * 16 + lk * 8) * 2;
            ldsm_x4(aH, ad);
            ldsm_x4(aL, ad + (OFF_ALO - OFF_AHI));
            #pragma unroll
            for (int nt = 0; nt < 16; nt++) {
                const uint32_t bd = sb + OFF_W1 + (nt * 8 + brow) * 144
                                  + (ks * 16 + bk * 8) * 2;
                uint32_t b0, b1r;
                ldsm_x2(b0, b1r, bd);
                mma_f16(acc[nt], aH, b0, b1r);
                mma_f16(acc[nt], aL, b0, b1r);
            }
        }
        // ---- SiLU(+b1) -> fp16 frags in registers (C-frag == next A-frag) --
        uint32_t sh[16][2];
        #pragma unroll
        for (int nt = 0; nt < 16; nt++) {
            const int h0 = nt * 8 + 2 * tig;
            const float bi0 = b1s[h0], bi1 = b1s[h0 + 1];
            sh[nt][0] = packh(__float2half_rn(silu_f(acc[nt][0] + bi0)),
                              __float2half_rn(silu_f(acc[nt][1] + bi1)));
            sh[nt][1] = packh(__float2half_rn(silu_f(acc[nt][2] + bi0)),
                              __float2half_rn(silu_f(acc[nt][3] + bi1)));
        }

        // ---- GEMM2: [16px x 64o] per warp, K=128, A from registers ----
        float acc2[8][4];
        #pragma unroll
        for (int nt = 0; nt < 8; nt++)
            #pragma unroll
            for (int i = 0; i < 4; i++) acc2[nt][i] = 0.f;
        #pragma unroll
        for (int ks = 0; ks < 8; ks++) {
            const uint32_t aF[4] = { sh[2 * ks][0], sh[2 * ks][1],
                                     sh[2 * ks + 1][0], sh[2 * ks + 1][1] };
            #pragma unroll
            for (int nt = 0; nt < 8; nt++) {
                const uint32_t bd = sb + OFF_W2 + (nt * 8 + brow) * 272
                                  + (ks * 16 + bk * 8) * 2;
                uint32_t b0, b1r;
                ldsm_x2(b0, b1r, bd);
                mma_f16(acc2[nt], aF, b0, b1r);
            }
        }

        CP_WAIT0();
        __syncthreads();   // z2 raw landed

        // ---- epilogue A: odd outputs, c=0..31 (residual from A hi/lo) ----
        {
            const int c = lane;                  // conflict-free A access
            #pragma unroll 4
            for (int it = 0; it < 16; it++) {
                const int px = w * 16 + it;
                const uint32_t aw = (uint32_t)px * 144 + c * 4;
                const uint32_t ah = *(const uint32_t*)(smc + OFF_AHI + aw);
                const uint32_t al = *(const uint32_t*)(smc + OFF_ALO + aw);
                const float zn = __half2float(__high2half(*(const __half2*)&ah))
                               + __half2float(__high2half(*(const __half2*)&al));
                const float resid = zn * sg + mu;                 // z0[2c+1]
                const float nz2 = (z2s[c * Z2STR + px] - mu) * rs;
                ob[(size_t)(2 * c + 1) * HW + p0 + px] = nz2 + resid;
            }
        }
        // ---- epilogue B: odd outputs, c=32..63 (residual from z2 tile) ----
        #pragma unroll
        for (int k = 0; k < 4; k++) {
            const int i = tid + k * 256;          // 32ch x 32 float4
            const int c = 32 + (i >> 5);
            const int f = (i & 31) * 4;
            const float4 zv = *(const float4*)(z2s + c * Z2STR + f);
            const float4 rv = *(const float4*)(z2s + (2 * (c - 32) + 1) * Z2STR + f);
            float4 ov;
            ov.x = (zv.x - mu) * rs + rv.x; ov.y = (zv.y - mu) * rs + rv.y;
            ov.z = (zv.z - mu) * rs + rv.z; ov.w = (zv.w - mu) * rs + rv.w;
            *(float4*)(ob + (size_t)(2 * c + 1) * HW + p0 + f) = ov;
        }
        // ---- epilogue C: even outputs from y frags (+ residual) ----
        {
            const int px0 = w * 16 + g;
            #pragma unroll
            for (int nt = 0; nt < 8; nt++) {
                const int o0 = nt * 8 + 2 * tig;
                float r[4];                       // residuals (o0,px0)(o0+1,px0)(o0,px0+8)(o0+1,px0+8)
                if (nt < 4) {                     // o0 < 32: z0[2o] via A reconstruct (lo half)
                    #pragma unroll
                    for (int q = 0; q < 2; q++) {       // px0, px0+8
                        const int px = px0 + q * 8;
                        #pragma unroll
                        for (int j = 0; j < 2; j++) {   // o0, o0+1
                            const uint32_t aw = (uint32_t)px * 144 + (o0 + j) * 4;
                            const uint32_t ah = *(const uint32_t*)(smc + OFF_AHI + aw);
                            const uint32_t al = *(const uint32_t*)(smc + OFF_ALO + aw);
                            const float zn = __half2float(__low2half(*(const __half2*)&ah))
                                           + __half2float(__low2half(*(const __half2*)&al));
                            r[q * 2 + j] = zn * sg + mu;
                        }
                    }
                } else {                          // o0 >= 32: z0[2o] = z2 ch 2(o-32)
                    r[0] = z2s[(2 * (o0     - 32)) * Z2STR + px0];
                    r[1] = z2s[(2 * (o0 + 1 - 32)) * Z2STR + px0];
                    r[2] = z2s[(2 * (o0     - 32)) * Z2STR + px0 + 8];
                    r[3] = z2s[(2 * (o0 + 1 - 32)) * Z2STR + px0 + 8];
                }
                ob[(size_t)(2 * o0)       * HW + p0 + px0]     = acc2[nt][0] + b2s[o0]     + r[0];
                ob[(size_t)(2 * (o0 + 1)) * HW + p0 + px0]     = acc2[nt][1] + b2s[o0 + 1] + r[1];
                ob[(size_t)(2 * o0)       * HW + p0 + px0 + 8] = acc2[nt][2] + b2s[o0]     + r[2];
                ob[(size_t)(2 * (o0 + 1)) * HW + p0 + px0 + 8] = acc2[nt][3] + b2s[o0 + 1] + r[3];
            }
        }
    }
}

// ---------------------------------------------------------------------------
extern "C" void kernel_launch(void* const* d_in, const int* in_sizes, int n_in,
                              void* d_out, int out_size) {
    const float* z0 = (const float*)d_in[0];
    const float* w1 = (const float*)d_in[1];
    const float* b1 = (const float*)d_in[2];
    const float* w2 = (const float*)d_in[3];
    const float* b2 = (const float*)d_in[4];
    float* out = (float*)d_out;

    static bool attr_set = false;
    if (!attr_set) {
        cudaFuncSetAttribute(cp_main_kernel,
                             cudaFuncAttributeMaxDynamicSharedMemorySize,
                             SMEM_MAIN);
        attr_set = true;
    }

    cp_stats_kernel<<<dim3(RED_BLOCKS, NSAMP), RED_THREADS>>>(z0);
    cp_finalize_kernel<<<1, 256>>>(w1, w2);
    cp_main_kernel<<<MAIN_GRID, 256, SMEM_MAIN>>>(z0, b1, b2, out);
}

// round 14
// speedup vs baseline: 1.3587x; 1.3587x over previous
#include <cuda_runtime.h>
#include <cuda_fp16.h>
#include <cstdint>

// ---------------------------------------------------------------------------
// ChannelProjection via mma.sync (HMMA fp16, base-target ISA).
// R13 = R11 skeleton + register-chain GEMM2 + smem-resident residuals.
//   - GEMM1 C-frags become GEMM2 A-frags in registers (no S smem tile).
//   - Raw z1 tile stays in smem all tile: z1-channel residuals read from
//     smem; z2-channel residuals are same-tile L2 hits. All accesses float4.
// 107KB smem, 2 CTAs/SM, 5 barriers/tile.
// ---------------------------------------------------------------------------

#define C_TOT   128
#define CC      64
#define HW      36864
#define NSAMP   16
#define CHW     (C_TOT * HW)
#define NPIX    (NSAMP * HW)
#define RED_BLOCKS  64
#define RED_THREADS 256

#define TPB       4                       // 128-px tiles per block
#define BLOCKS_PER_SAMPLE 72              // 72 * 4 * 128 = 36864 px
#define MAIN_GRID (NSAMP * BLOCKS_PER_SAMPLE)   // 1152
#define STG_STR 132                       // fp32 row stride of raw-z1 tile

// smem offsets; A/W1 rows 144B (72 fp16), W2 rows 272B (136 fp16)
#define OFF_W1    0          // [128h][72k]    18432
#define OFF_W2    18432      // [64o][136h]    17408
#define OFF_AHI   35840      // [128px][72k]   18432 (Y fp32 [64o][132] aliases A)
#define OFF_ALO   54272      //                18432
#define OFF_STG   72704      // [64c][132] f32 33792 (raw z1, alive whole tile)
#define OFF_B1    106496     // 128 f32
#define OFF_B2    107008     // 64 f32
#define SMEM_MAIN 107264

__device__ float g_psum[NSAMP * RED_BLOCKS];
__device__ float g_psq [NSAMP * RED_BLOCKS];
__device__ float g_mu  [NSAMP];
__device__ float g_rs  [NSAMP];
__device__ uint4 g_w1h[1152];   // 128*72 fp16
__device__ uint4 g_w2h[1088];   // 64*136 fp16

// ---------------- helpers ---------------------------------------------------
__device__ __forceinline__ uint32_t smem_u32(const void* p) {
    uint32_t a;
    asm("{ .reg .u64 t; cvta.to.shared.u64 t, %1; cvt.u32.u64 %0, t; }"
        : "=r"(a) : "l"(p));
    return a;
}
__device__ __forceinline__ void ldsm_x4(uint32_t (&r)[4], uint32_t addr) {
    asm volatile("ldmatrix.sync.aligned.m8n8.x4.shared.b16 {%0,%1,%2,%3}, [%4];"
                 : "=r"(r[0]), "=r"(r[1]), "=r"(r[2]), "=r"(r[3]) : "r"(addr));
}
__device__ __forceinline__ void ldsm_x2(uint32_t& r0, uint32_t& r1, uint32_t addr) {
    asm volatile("ldmatrix.sync.aligned.m8n8.x2.shared.b16 {%0,%1}, [%2];"
                 : "=r"(r0), "=r"(r1) : "r"(addr));
}
__device__ __forceinline__ void mma_f16(float (&c)[4], const uint32_t (&a)[4],
                                        uint32_t b0, uint32_t b1) {
    asm volatile(
        "mma.sync.aligned.m16n8k16.row.col.f32.f16.f16.f32 "
        "{%0,%1,%2,%3}, {%4,%5,%6,%7}, {%8,%9}, {%0,%1,%2,%3};"
        : "+f"(c[0]), "+f"(c[1]), "+f"(c[2]), "+f"(c[3])
        : "r"(a[0]), "r"(a[1]), "r"(a[2]), "r"(a[3]), "r"(b0), "r"(b1));
}
__device__ __forceinline__ uint32_t packh(__half a, __half b) {
    __half2 h; h.x = a; h.y = b;
    return *(uint32_t*)&h;
}
__device__ __forceinline__ void split2h(float v0, float v1, uint32_t& hi, uint32_t& lo) {
    const __half h0 = __float2half_rn(v0);
    const __half h1 = __float2half_rn(v1);
    const __half l0 = __float2half_rn(v0 - __half2float(h0));
    const __half l1 = __float2half_rn(v1 - __half2float(h1));
    hi = packh(h0, h1);
    lo = packh(l0, l1);
}
__device__ __forceinline__ float silu_f(float h) {
    return __fdividef(h, 1.f + __expf(-h));
}

// ---------------- stage 1: per-sample partial sums --------------------------
__global__ void cp_stats_kernel(const float* __restrict__ z0) {
    const int b = blockIdx.y;
    const float4* z4 = (const float4*)(z0 + (size_t)b * CHW);
    const int n4 = CHW / 4;
    float s = 0.f, q = 0.f;
    for (int i = blockIdx.x * RED_THREADS + threadIdx.x; i < n4;
         i += RED_BLOCKS * RED_THREADS) {
        float4 v = z4[i];
        s += (v.x + v.y) + (v.z + v.w);
        q += (v.x * v.x + v.y * v.y) + (v.z * v.z + v.w * v.w);
    }
    #pragma unroll
    for (int off = 16; off; off >>= 1) {
        s += __shfl_down_sync(0xffffffffu, s, off);
        q += __shfl_down_sync(0xffffffffu, q, off);
    }
    __shared__ float ss[RED_THREADS / 32], sq[RED_THREADS / 32];
    const int w = threadIdx.x >> 5;
    if ((threadIdx.x & 31) == 0) { ss[w] = s; sq[w] = q; }
    __syncthreads();
    if (threadIdx.x == 0) {
        float S = 0.f, Q = 0.f;
        #pragma unroll
        for (int i = 0; i < RED_THREADS / 32; i++) { S += ss[i]; Q += sq[i]; }
        g_psum[b * RED_BLOCKS + blockIdx.x] = S;
        g_psq [b * RED_BLOCKS + blockIdx.x] = Q;
    }
}

// ---------------- stage 2: finalize + fp16 weights --------------------------
__global__ void cp_finalize_kernel(const float* __restrict__ w1,
                                   const float* __restrict__ w2) {
    const int t = threadIdx.x;   // 256
    if (t < NSAMP) {
        float S = 0.f, Q = 0.f;
        for (int i = 0; i < RED_BLOCKS; i++) {
            S += g_psum[t * RED_BLOCKS + i];
            Q += g_psq [t * RED_BLOCKS + i];
        }
        const float inv_n = 1.f / (float)CHW;
        const float mu  = S * inv_n;
        const float var = Q * inv_n - mu * mu;
        g_mu[t] = mu;
        g_rs[t] = rsqrtf(var + 1e-5f);
    }
    __half* w1h = (__half*)g_w1h;
    __half* w2h = (__half*)g_w2h;
    for (int i = t; i < 128 * 64; i += 256) {      // w1[h][k] -> [h][72]
        const int h = i >> 6, k = i & 63;
        w1h[h * 72 + k] = __float2half_rn(w1[h * 64 + k]);
    }
    for (int i = t; i < 64 * 128; i += 256) {      // w2[o][h] -> [o][136]
        const int o = i >> 7, h = i & 127;
        w2h[o * 136 + h] = __float2half_rn(w2[o * 128 + h]);
    }
}

// ---------------- stage 3: HMMA main kernel (2 CTAs/SM) ---------------------
__global__ void __launch_bounds__(256, 2)
cp_main_kernel(const float* __restrict__ z0,
               const float* __restrict__ b1,
               const float* __restrict__ b2,
               float* __restrict__ out) {
    extern __shared__ char smc[];
    const uint32_t sb = smem_u32(smc);
    const int tid = threadIdx.x;
    const int w = tid >> 5, lane = tid & 31;
    const int g = lane >> 2, tig = lane & 3;
    const int lrow = lane & 15, lk = lane >> 4;          // ldsm.x4 mapping
    const int brow = lane & 7,  bk = (lane >> 3) & 1;    // ldsm.x2 mapping

    // ---- stage weights + biases ----
    for (int i = tid; i < 1152; i += 256) ((uint4*)(smc + OFF_W1))[i] = g_w1h[i];
    for (int i = tid; i < 1088; i += 256) ((uint4*)(smc + OFF_W2))[i] = g_w2h[i];
    float* b1s = (float*)(smc + OFF_B1);
    float* b2s = (float*)(smc + OFF_B2);
    if (tid < 128) b1s[tid] = b1[tid];
    if (tid < 64)  b2s[tid] = b2[tid];

    const int b = blockIdx.x / BLOCKS_PER_SAMPLE;
    const float* zb = z0 + (size_t)b * CHW;
    float*       ob = out + (size_t)b * CHW;
    const int p_base = (blockIdx.x % BLOCKS_PER_SAMPLE) * (TPB * 128);
    const float mu = g_mu[b];
    const float rs = g_rs[b];
    float* stg = (float*)(smc + OFF_STG);    // raw z1 [64c][132], whole tile
    float* Y   = (float*)(smc + OFF_AHI);    // fp32 [64o][132] aliases A

    for (int tl = 0; tl < TPB; tl++) {
        const int p0 = p_base + tl * 128;
        __syncthreads();   // prev tile write-out reads of stg/Y done

        // ---- phase 1: raw z1 -> stg (8 independent LDG.128 / thread) ----
        #pragma unroll
        for (int k = 0; k < 8; k++) {
            const int i = tid + k * 256;          // 64ch x 32 float4
            const int c = i >> 5, f = (i & 31) * 4;
            *(float4*)(stg + c * STG_STR + f) = *(const float4*)(zb + (size_t)c * HW + p0 + f);
        }
        __syncthreads();

        // ---- phase 2: normalize + split -> A hi/lo fp16 [px][72] ----
        #pragma unroll
        for (int k = 0; k < 4; k++) {
            const int i = tid + k * 256;          // 128px x 8 c-groups
            const int px = i & 127, c0 = (i >> 7) * 8;
            uint32_t hiw[4], low[4];
            #pragma unroll
            for (int j = 0; j < 4; j++) {
                const float v0 = (stg[(c0 + 2 * j)     * STG_STR + px] - mu) * rs;
                const float v1 = (stg[(c0 + 2 * j + 1) * STG_STR + px] - mu) * rs;
                split2h(v0, v1, hiw[j], low[j]);
            }
            *(uint4*)(smc + OFF_AHI + px * 144 + c0 * 2) = make_uint4(hiw[0], hiw[1], hiw[2], hiw[3]);
            *(uint4*)(smc + OFF_ALO + px * 144 + c0 * 2) = make_uint4(low[0], low[1], low[2], low[3]);
        }
        __syncthreads();   // A ready; stg still live (read-only from here)

        // ---- z2 stream, c<32: residual z0[2c+1] from stg (z1 ch 2c+1) ----
        #pragma unroll
        for (int k = 0; k < 4; k++) {
            const int i = tid + k * 256;          // 32ch x 32 float4
            const int c = i >> 5, f = (i & 31) * 4;
            const float4 zv = *(const float4*)(zb + (size_t)(CC + c) * HW + p0 + f);
            const float4 rv = *(const float4*)(stg + (2 * c + 1) * STG_STR + f);
            float4 ov;
            ov.x = (zv.x - mu) * rs + rv.x; ov.y = (zv.y - mu) * rs + rv.y;
            ov.z = (zv.z - mu) * rs + rv.z; ov.w = (zv.w - mu) * rs + rv.w;
            *(float4*)(ob + (size_t)(2 * c + 1) * HW + p0 + f) = ov;
        }
        // ---- z2 stream, c>=32: residual z0[2c+1] = z2 ch (same-tile L2) ----
        #pragma unroll
        for (int k = 0; k < 4; k++) {
            const int i = tid + k * 256;          // 32ch x 32 float4
            const int c = 32 + (i >> 5), f = (i & 31) * 4;
            const float4 zv = *(const float4*)(zb + (size_t)(CC + c) * HW + p0 + f);
            const float4 rv = *(const float4*)(zb + (size_t)(2 * c + 1) * HW + p0 + f);
            float4 ov;
            ov.x = (zv.x - mu) * rs + rv.x; ov.y = (zv.y - mu) * rs + rv.y;
            ov.z = (zv.z - mu) * rs + rv.z; ov.w = (zv.w - mu) * rs + rv.w;
            *(float4*)(ob + (size_t)(2 * c + 1) * HW + p0 + f) = ov;
        }

        // ---- GEMM1: [16px x 128h] per warp, K=64, 2 split passes ----
        float acc[16][4];
        #pragma unroll
        for (int nt = 0; nt < 16; nt++)
            #pragma unroll
            for (int i = 0; i < 4; i++) acc[nt][i] = 0.f;
        #pragma unroll
        for (int ks = 0; ks < 4; ks++) {
            uint32_t aH[4], aL[4];
            const uint32_t ad = sb + OFF_AHI + (w * 16 + lrow) * 144 + (ks * 16 + lk * 8) * 2;
            ldsm_x4(aH, ad);
            ldsm_x4(aL, ad + (OFF_ALO - OFF_AHI));
            #pragma unroll
            for (int nt = 0; nt < 16; nt++) {
                const uint32_t bd = sb + OFF_W1 + (nt * 8 + brow) * 144
                                  + (ks * 16 + bk * 8) * 2;
                uint32_t b0, b1r;
                ldsm_x2(b0, b1r, bd);
                mma_f16(acc[nt], aH, b0, b1r);
                mma_f16(acc[nt], aL, b0, b1r);
            }
        }
        // ---- SiLU(+b1) -> fp16 frags in registers (C-frag == next A-frag) --
        uint32_t sh[16][2];
        #pragma unroll
        for (int nt = 0; nt < 16; nt++) {
            const int h0 = nt * 8 + 2 * tig;
            const float bi0 = b1s[h0], bi1 = b1s[h0 + 1];
            sh[nt][0] = packh(__float2half_rn(silu_f(acc[nt][0] + bi0)),
                              __float2half_rn(silu_f(acc[nt][1] + bi1)));
            sh[nt][1] = packh(__float2half_rn(silu_f(acc[nt][2] + bi0)),
                              __float2half_rn(silu_f(acc[nt][3] + bi1)));
        }
        __syncthreads();   // all A reads done -> Y (A alias) is free

        // ---- GEMM2: [16px x 64o] per warp, K=128, A from registers ----
        float acc2[8][4];
        #pragma unroll
        for (int nt = 0; nt < 8; nt++)
            #pragma unroll
            for (int i = 0; i < 4; i++) acc2[nt][i] = 0.f;
        #pragma unroll
        for (int ks = 0; ks < 8; ks++) {
            const uint32_t aF[4] = { sh[2 * ks][0], sh[2 * ks][1],
                                     sh[2 * ks + 1][0], sh[2 * ks + 1][1] };
            #pragma unroll
            for (int nt = 0; nt < 8; nt++) {
                const uint32_t bd = sb + OFF_W2 + (nt * 8 + brow) * 272
                                  + (ks * 16 + bk * 8) * 2;
                uint32_t b0, b1r;
                ldsm_x2(b0, b1r, bd);
                mma_f16(acc2[nt], aF, b0, b1r);
            }
        }
        // ---- stash y+b2 into Y [o][132] (conflict-free) ----
        const int pxl = w * 16 + g;
        #pragma unroll
        for (int nt = 0; nt < 8; nt++) {
            const int o0 = nt * 8 + 2 * tig;
            Y[o0 * 132 + pxl]           = acc2[nt][0] + b2s[o0];
            Y[(o0 + 1) * 132 + pxl]     = acc2[nt][1] + b2s[o0 + 1];
            Y[o0 * 132 + pxl + 8]       = acc2[nt][2] + b2s[o0];
            Y[(o0 + 1) * 132 + pxl + 8] = acc2[nt][3] + b2s[o0 + 1];
        }
        __syncthreads();

        // ---- write-out o<32: residual z0[2o] from stg (z1 ch 2o) ----
        #pragma unroll
        for (int k = 0; k < 4; k++) {
            const int i = tid + k * 256;          // 32o x 32 float4
            const int o = i >> 5, f = (i & 31) * 4;
            const float4 yv = *(const float4*)(Y + o * 132 + f);
            const float4 rv = *(const float4*)(stg + (2 * o) * STG_STR + f);
            float4 ov;
            ov.x = yv.x + rv.x; ov.y = yv.y + rv.y;
            ov.z = yv.z + rv.z; ov.w = yv.w + rv.w;
            *(float4*)(ob + (size_t)(2 * o) * HW + p0 + f) = ov;
        }
        // ---- write-out o>=32: residual z0[2o] = z2 ch (same-tile L2) ----
        #pragma unroll
        for (int k = 0; k < 4; k++) {
            const int i = tid + k * 256;          // 32o x 32 float4
            const int o = 32 + (i >> 5), f = (i & 31) * 4;
            const float4 yv = *(const float4*)(Y + o * 132 + f);
            const float4 rv = *(const float4*)(zb + (size_t)(2 * o) * HW + p0 + f);
            float4 ov;
            ov.x = yv.x + rv.x; ov.y = yv.y + rv.y;
            ov.z = yv.z + rv.z; ov.w = yv.w + rv.w;
            *(float4*)(ob + (size_t)(2 * o) * HW + p0 + f) = ov;
        }
    }
}

// ---------------------------------------------------------------------------
extern "C" void kernel_launch(void* const* d_in, const int* in_sizes, int n_in,
                              void* d_out, int out_size) {
    const float* z0 = (const float*)d_in[0];
    const float* w1 = (const float*)d_in[1];
    const float* b1 = (const float*)d_in[2];
    const float* w2 = (const float*)d_in[3];
    const float* b2 = (const float*)d_in[4];
    float* out = (float*)d_out;

    static bool attr_set = false;
    if (!attr_set) {
        cudaFuncSetAttribute(cp_main_kernel,
                             cudaFuncAttributeMaxDynamicSharedMemorySize,
                             SMEM_MAIN);
        attr_set = true;
    }

    cp_stats_kernel<<<dim3(RED_BLOCKS, NSAMP), RED_THREADS>>>(z0);
    cp_finalize_kernel<<<1, 256>>>(w1, w2);
    cp_main_kernel<<<MAIN_GRID, 256, SMEM_MAIN>>>(z0, b1, b2, out);
}

// round 16
// speedup vs baseline: 1.4536x; 1.0699x over previous
#include <cuda_runtime.h>
#include <cuda_fp16.h>
#include <cstdint>

// ---------------------------------------------------------------------------
// ChannelProjection via mma.sync (HMMA fp16, base-target ISA).
// R15 = R14 with the Y/STG smem overlap bug fixed:
//   union(A fp16 [128px][72k] = 18432 B, Y fp32 [64o][132] = 33792 B) is now
//   sized for Y; STG placed after it. (R14 let Y overflow 15KB into STG,
//   corrupting the residual source rows -> rel_err 0.30.)
//   - GEMM1 single-pass fp16 (-33% mma), GEMM2 A-frags from registers.
//   - Residuals: z1-channels from resident raw tile, z2-channels via L2.
// 104KB smem, 2 CTAs/SM, 5 barriers/tile.
// ---------------------------------------------------------------------------

#define C_TOT   128
#define CC      64
#define HW      36864
#define NSAMP   16
#define CHW     (C_TOT * HW)
#define NPIX    (NSAMP * HW)
#define RED_BLOCKS  64
#define RED_THREADS 256

#define TPB       4                       // 128-px tiles per block
#define BLOCKS_PER_SAMPLE 72              // 72 * 4 * 128 = 36864 px
#define MAIN_GRID (NSAMP * BLOCKS_PER_SAMPLE)   // 1152
#define STG_STR 132                       // fp32 row stride of raw-z1 tile

// smem offsets; A/W1 rows 144B (72 fp16), W2 rows 272B (136 fp16)
#define OFF_W1    0          // [128h][72k]    18432
#define OFF_W2    18432      // [64o][136h]    17408
#define OFF_A     35840      // union: A fp16 (18432) / Y fp32 [64o][132] (33792)
#define OFF_STG   69632      // [64c][132] f32 33792 (raw z1, alive whole tile)
#define OFF_B1    103424     // 128 f32
#define OFF_B2    103936     // 64 f32
#define SMEM_MAIN 104192

__device__ float g_psum[NSAMP * RED_BLOCKS];
__device__ float g_psq [NSAMP * RED_BLOCKS];
__device__ float g_mu  [NSAMP];
__device__ float g_rs  [NSAMP];
__device__ uint4 g_w1h[1152];   // 128*72 fp16
__device__ uint4 g_w2h[1088];   // 64*136 fp16

// ---------------- helpers ---------------------------------------------------
__device__ __forceinline__ uint32_t smem_u32(const void* p) {
    uint32_t a;
    asm("{ .reg .u64 t; cvta.to.shared.u64 t, %1; cvt.u32.u64 %0, t; }"
        : "=r"(a) : "l"(p));
    return a;
}
__device__ __forceinline__ void ldsm_x4(uint32_t (&r)[4], uint32_t addr) {
    asm volatile("ldmatrix.sync.aligned.m8n8.x4.shared.b16 {%0,%1,%2,%3}, [%4];"
                 : "=r"(r[0]), "=r"(r[1]), "=r"(r[2]), "=r"(r[3]) : "r"(addr));
}
__device__ __forceinline__ void ldsm_x2(uint32_t& r0, uint32_t& r1, uint32_t addr) {
    asm volatile("ldmatrix.sync.aligned.m8n8.x2.shared.b16 {%0,%1}, [%2];"
                 : "=r"(r0), "=r"(r1) : "r"(addr));
}
__device__ __forceinline__ void mma_f16(float (&c)[4], const uint32_t (&a)[4],
                                        uint32_t b0, uint32_t b1) {
    asm volatile(
        "mma.sync.aligned.m16n8k16.row.col.f32.f16.f16.f32 "
        "{%0,%1,%2,%3}, {%4,%5,%6,%7}, {%8,%9}, {%0,%1,%2,%3};"
        : "+f"(c[0]), "+f"(c[1]), "+f"(c[2]), "+f"(c[3])
        : "r"(a[0]), "r"(a[1]), "r"(a[2]), "r"(a[3]), "r"(b0), "r"(b1));
}
__device__ __forceinline__ uint32_t packh(__half a, __half b) {
    __half2 h; h.x = a; h.y = b;
    return *(uint32_t*)&h;
}
__device__ __forceinline__ float silu_f(float h) {
    return __fdividef(h, 1.f + __expf(-h));
}

// ---------------- stage 1: per-sample partial sums --------------------------
__global__ void cp_stats_kernel(const float* __restrict__ z0) {
    const int b = blockIdx.y;
    const float4* z4 = (const float4*)(z0 + (size_t)b * CHW);
    const int n4 = CHW / 4;
    float s = 0.f, q = 0.f;
    for (int i = blockIdx.x * RED_THREADS + threadIdx.x; i < n4;
         i += RED_BLOCKS * RED_THREADS) {
        float4 v = z4[i];
        s += (v.x + v.y) + (v.z + v.w);
        q += (v.x * v.x + v.y * v.y) + (v.z * v.z + v.w * v.w);
    }
    #pragma unroll
    for (int off = 16; off; off >>= 1) {
        s += __shfl_down_sync(0xffffffffu, s, off);
        q += __shfl_down_sync(0xffffffffu, q, off);
    }
    __shared__ float ss[RED_THREADS / 32], sq[RED_THREADS / 32];
    const int w = threadIdx.x >> 5;
    if ((threadIdx.x & 31) == 0) { ss[w] = s; sq[w] = q; }
    __syncthreads();
    if (threadIdx.x == 0) {
        float S = 0.f, Q = 0.f;
        #pragma unroll
        for (int i = 0; i < RED_THREADS / 32; i++) { S += ss[i]; Q += sq[i]; }
        g_psum[b * RED_BLOCKS + blockIdx.x] = S;
        g_psq [b * RED_BLOCKS + blockIdx.x] = Q;
    }
}

// ---------------- stage 2: finalize + fp16 weights --------------------------
__global__ void cp_finalize_kernel(const float* __restrict__ w1,
                                   const float* __restrict__ w2) {
    const int t = threadIdx.x;   // 256
    if (t < NSAMP) {
        float S = 0.f, Q = 0.f;
        for (int i = 0; i < RED_BLOCKS; i++) {
            S += g_psum[t * RED_BLOCKS + i];
            Q += g_psq [t * RED_BLOCKS + i];
        }
        const float inv_n = 1.f / (float)CHW;
        const float mu  = S * inv_n;
        const float var = Q * inv_n - mu * mu;
        g_mu[t] = mu;
        g_rs[t] = rsqrtf(var + 1e-5f);
    }
    __half* w1h = (__half*)g_w1h;
    __half* w2h = (__half*)g_w2h;
    for (int i = t; i < 128 * 64; i += 256) {      // w1[h][k] -> [h][72]
        const int h = i >> 6, k = i & 63;
        w1h[h * 72 + k] = __float2half_rn(w1[h * 64 + k]);
    }
    for (int i = t; i < 64 * 128; i += 256) {      // w2[o][h] -> [o][136]
        const int o = i >> 7, h = i & 127;
        w2h[o * 136 + h] = __float2half_rn(w2[o * 128 + h]);
    }
}

// ---------------- stage 3: HMMA main kernel (2 CTAs/SM) ---------------------
__global__ void __launch_bounds__(256, 2)
cp_main_kernel(const float* __restrict__ z0,
               const float* __restrict__ b1,
               const float* __restrict__ b2,
               float* __restrict__ out) {
    extern __shared__ char smc[];
    const uint32_t sb = smem_u32(smc);
    const int tid = threadIdx.x;
    const int w = tid >> 5, lane = tid & 31;
    const int g = lane >> 2, tig = lane & 3;
    const int lrow = lane & 15, lk = lane >> 4;          // ldsm.x4 mapping
    const int brow = lane & 7,  bk = (lane >> 3) & 1;    // ldsm.x2 mapping

    // ---- stage weights + biases ----
    for (int i = tid; i < 1152; i += 256) ((uint4*)(smc + OFF_W1))[i] = g_w1h[i];
    for (int i = tid; i < 1088; i += 256) ((uint4*)(smc + OFF_W2))[i] = g_w2h[i];
    float* b1s = (float*)(smc + OFF_B1);
    float* b2s = (float*)(smc + OFF_B2);
    if (tid < 128) b1s[tid] = b1[tid];
    if (tid < 64)  b2s[tid] = b2[tid];

    const int b = blockIdx.x / BLOCKS_PER_SAMPLE;
    const float* zb = z0 + (size_t)b * CHW;
    float*       ob = out + (size_t)b * CHW;
    const int p_base = (blockIdx.x % BLOCKS_PER_SAMPLE) * (TPB * 128);
    const float mu = g_mu[b];
    const float rs = g_rs[b];
    float* stg = (float*)(smc + OFF_STG);    // raw z1 [64c][132], whole tile
    float* Y   = (float*)(smc + OFF_A);      // fp32 [64o][132], unions with A

    for (int tl = 0; tl < TPB; tl++) {
        const int p0 = p_base + tl * 128;
        __syncthreads();   // prev tile write-out reads of stg/Y done

        // ---- phase 1: raw z1 -> stg (8 independent LDG.128 / thread) ----
        #pragma unroll
        for (int k = 0; k < 8; k++) {
            const int i = tid + k * 256;          // 64ch x 32 float4
            const int c = i >> 5, f = (i & 31) * 4;
            *(float4*)(stg + c * STG_STR + f) = *(const float4*)(zb + (size_t)c * HW + p0 + f);
        }
        __syncthreads();

        // ---- phase 2: normalize -> A fp16 [px][72] (single precision pass) -
        #pragma unroll
        for (int k = 0; k < 4; k++) {
            const int i = tid + k * 256;          // 128px x 8 c-groups
            const int px = i & 127, c0 = (i >> 7) * 8;
            uint32_t hw[4];
            #pragma unroll
            for (int j = 0; j < 4; j++) {
                const float v0 = (stg[(c0 + 2 * j)     * STG_STR + px] - mu) * rs;
                const float v1 = (stg[(c0 + 2 * j + 1) * STG_STR + px] - mu) * rs;
                hw[j] = packh(__float2half_rn(v0), __float2half_rn(v1));
            }
            *(uint4*)(smc + OFF_A + px * 144 + c0 * 2) = make_uint4(hw[0], hw[1], hw[2], hw[3]);
        }
        __syncthreads();   // A ready; stg still live (read-only from here)

        // ---- z2 stream, c<32: residual z0[2c+1] from stg (z1 ch 2c+1) ----
        #pragma unroll
        for (int k = 0; k < 4; k++) {
            const int i = tid + k * 256;          // 32ch x 32 float4
            const int c = i >> 5, f = (i & 31) * 4;
            const float4 zv = *(const float4*)(zb + (size_t)(CC + c) * HW + p0 + f);
            const float4 rv = *(const float4*)(stg + (2 * c + 1) * STG_STR + f);
            float4 ov;
            ov.x = (zv.x - mu) * rs + rv.x; ov.y = (zv.y - mu) * rs + rv.y;
            ov.z = (zv.z - mu) * rs + rv.z; ov.w = (zv.w - mu) * rs + rv.w;
            *(float4*)(ob + (size_t)(2 * c + 1) * HW + p0 + f) = ov;
        }
        // ---- z2 stream, c>=32: residual z0[2c+1] = z2 ch (same-tile L2) ----
        #pragma unroll
        for (int k = 0; k < 4; k++) {
            const int i = tid + k * 256;          // 32ch x 32 float4
            const int c = 32 + (i >> 5), f = (i & 31) * 4;
            const float4 zv = *(const float4*)(zb + (size_t)(CC + c) * HW + p0 + f);
            const float4 rv = *(const float4*)(zb + (size_t)(2 * c + 1) * HW + p0 + f);
            float4 ov;
            ov.x = (zv.x - mu) * rs + rv.x; ov.y = (zv.y - mu) * rs + rv.y;
            ov.z = (zv.z - mu) * rs + rv.z; ov.w = (zv.w - mu) * rs + rv.w;
            *(float4*)(ob + (size_t)(2 * c + 1) * HW + p0 + f) = ov;
        }

        // ---- GEMM1: [16px x 128h] per warp, K=64, single pass ----
        float acc[16][4];
        #pragma unroll
        for (int nt = 0; nt < 16; nt++)
            #pragma unroll
            for (int i = 0; i < 4; i++) acc[nt][i] = 0.f;
        #pragma unroll
        for (int ks = 0; ks < 4; ks++) {
            uint32_t aF[4];
            ldsm_x4(aF, sb + OFF_A + (w * 16 + lrow) * 144 + (ks * 16 + lk * 8) * 2);
            #pragma unroll
            for (int nt = 0; nt < 16; nt++) {
                const uint32_t bd = sb + OFF_W1 + (nt * 8 + brow) * 144
                                  + (ks * 16 + bk * 8) * 2;
                uint32_t b0, b1r;
                ldsm_x2(b0, b1r, bd);
                mma_f16(acc[nt], aF, b0, b1r);
            }
        }
        // ---- SiLU(+b1) -> fp16 frags in registers (C-frag == next A-frag) --
        uint32_t sh[16][2];
        #pragma unroll
        for (int nt = 0; nt < 16; nt++) {
            const int h0 = nt * 8 + 2 * tig;
            const float bi0 = b1s[h0], bi1 = b1s[h0 + 1];
            sh[nt][0] = packh(__float2half_rn(silu_f(acc[nt][0] + bi0)),
                              __float2half_rn(silu_f(acc[nt][1] + bi1)));
            sh[nt][1] = packh(__float2half_rn(silu_f(acc[nt][2] + bi0)),
                              __float2half_rn(silu_f(acc[nt][3] + bi1)));
        }
        __syncthreads();   // all A reads done -> Y (A union) is free

        // ---- GEMM2: [16px x 64o] per warp, K=128, A from registers ----
        float acc2[8][4];
        #pragma unroll
        for (int nt = 0; nt < 8; nt++)
            #pragma unroll
            for (int i = 0; i < 4; i++) acc2[nt][i] = 0.f;
        #pragma unroll
        for (int ks = 0; ks < 8; ks++) {
            const uint32_t aF[4] = { sh[2 * ks][0], sh[2 * ks][1],
                                     sh[2 * ks + 1][0], sh[2 * ks + 1][1] };
            #pragma unroll
            for (int nt = 0; nt < 8; nt++) {
                const uint32_t bd = sb + OFF_W2 + (nt * 8 + brow) * 272
                                  + (ks * 16 + bk * 8) * 2;
                uint32_t b0, b1r;
                ldsm_x2(b0, b1r, bd);
                mma_f16(acc2[nt], aF, b0, b1r);
            }
        }
        // ---- stash y+b2 into Y [o][132] (conflict-free) ----
        const int pxl = w * 16 + g;
        #pragma unroll
        for (int nt = 0; nt < 8; nt++) {
            const int o0 = nt * 8 + 2 * tig;
            Y[o0 * 132 + pxl]           = acc2[nt][0] + b2s[o0];
            Y[(o0 + 1) * 132 + pxl]     = acc2[nt][1] + b2s[o0 + 1];
            Y[o0 * 132 + pxl + 8]       = acc2[nt][2] + b2s[o0];
            Y[(o0 + 1) * 132 + pxl + 8] = acc2[nt][3] + b2s[o0 + 1];
        }
        __syncthreads();

        // ---- write-out o<32: residual z0[2o] from stg (z1 ch 2o) ----
        #pragma unroll
        for (int k = 0; k < 4; k++) {
            const int i = tid + k * 256;          // 32o x 32 float4
            const int o = i >> 5, f = (i & 31) * 4;
            const float4 yv = *(const float4*)(Y + o * 132 + f);
            const float4 rv = *(const float4*)(stg + (2 * o) * STG_STR + f);
            float4 ov;
            ov.x = yv.x + rv.x; ov.y = yv.y + rv.y;
            ov.z = yv.z + rv.z; ov.w = yv.w + rv.w;
            *(float4*)(ob + (size_t)(2 * o) * HW + p0 + f) = ov;
        }
        // ---- write-out o>=32: residual z0[2o] = z2 ch (same-tile L2) ----
        #pragma unroll
        for (int k = 0; k < 4; k++) {
            const int i = tid + k * 256;          // 32o x 32 float4
            const int o = 32 + (i >> 5), f = (i & 31) * 4;
            const float4 yv = *(const float4*)(Y + o * 132 + f);
            const float4 rv = *(const float4*)(zb + (size_t)(2 * o) * HW + p0 + f);
            float4 ov;
            ov.x = yv.x + rv.x; ov.y = yv.y + rv.y;
            ov.z = yv.z + rv.z; ov.w = yv.w + rv.w;
            *(float4*)(ob + (size_t)(2 * o) * HW + p0 + f) = ov;
        }
    }
}

// ---------------------------------------------------------------------------
extern "C" void kernel_launch(void* const* d_in, const int* in_sizes, int n_in,
                              void* d_out, int out_size) {
    const float* z0 = (const float*)d_in[0];
    const float* w1 = (const float*)d_in[1];
    const float* b1 = (const float*)d_in[2];
    const float* w2 = (const float*)d_in[3];
    const float* b2 = (const float*)d_in[4];
    float* out = (float*)d_out;

    static bool attr_set = false;
    if (!attr_set) {
        cudaFuncSetAttribute(cp_main_kernel,
                             cudaFuncAttributeMaxDynamicSharedMemorySize,
                             SMEM_MAIN);
        attr_set = true;
    }

    cp_stats_kernel<<<dim3(RED_BLOCKS, NSAMP), RED_THREADS>>>(z0);
    cp_finalize_kernel<<<1, 256>>>(w1, w2);
    cp_main_kernel<<<MAIN_GRID, 256, SMEM_MAIN>>>(z0, b1, b2, out);
}

// round 17
// speedup vs baseline: 1.4699x; 1.0112x over previous
#include <cuda_runtime.h>
#include <cuda_fp16.h>
#include <cstdint>

// ---------------------------------------------------------------------------
// ChannelProjection via mma.sync (HMMA fp16, base-target ISA).
// R16 = R15 + memory/compute software pipelining:
//   - z2 stream interleaved into GEMM1's ks loop (2-slot LDG prefetch).
//   - next tile's z1 staging loads issued inside the write-out phase
//     (write-out residuals all come from global -> L2 hits; stg dies early).
//   - 4 barriers/tile. Same math as R15 (rel_err bit-identical).
// 104KB smem, 2 CTAs/SM.
// ---------------------------------------------------------------------------

#define C_TOT   128
#define CC      64
#define HW      36864
#define NSAMP   16
#define CHW     (C_TOT * HW)
#define NPIX    (NSAMP * HW)
#define RED_BLOCKS  64
#define RED_THREADS 256

#define TPB       4                       // 128-px tiles per block
#define BLOCKS_PER_SAMPLE 72              // 72 * 4 * 128 = 36864 px
#define MAIN_GRID (NSAMP * BLOCKS_PER_SAMPLE)   // 1152
#define STG_STR 132                       // fp32 row stride of raw-z1 tile

// smem offsets; A/W1 rows 144B (72 fp16), W2 rows 272B (136 fp16)
#define OFF_W1    0          // [128h][72k]    18432
#define OFF_W2    18432      // [64o][136h]    17408
#define OFF_A     35840      // union: A fp16 (18432) / Y fp32 [64o][132] (33792)
#define OFF_STG   69632      // [64c][132] f32 33792 (raw z1)
#define OFF_B1    103424     // 128 f32
#define OFF_B2    103936     // 64 f32
#define SMEM_MAIN 104192

__device__ float g_psum[NSAMP * RED_BLOCKS];
__device__ float g_psq [NSAMP * RED_BLOCKS];
__device__ float g_mu  [NSAMP];
__device__ float g_rs  [NSAMP];
__device__ uint4 g_w1h[1152];   // 128*72 fp16
__device__ uint4 g_w2h[1088];   // 64*136 fp16

// ---------------- helpers ---------------------------------------------------
__device__ __forceinline__ uint32_t smem_u32(const void* p) {
    uint32_t a;
    asm("{ .reg .u64 t; cvta.to.shared.u64 t, %1; cvt.u32.u64 %0, t; }"
        : "=r"(a) : "l"(p));
    return a;
}
__device__ __forceinline__ void ldsm_x4(uint32_t (&r)[4], uint32_t addr) {
    asm volatile("ldmatrix.sync.aligned.m8n8.x4.shared.b16 {%0,%1,%2,%3}, [%4];"
                 : "=r"(r[0]), "=r"(r[1]), "=r"(r[2]), "=r"(r[3]) : "r"(addr));
}
__device__ __forceinline__ void ldsm_x2(uint32_t& r0, uint32_t& r1, uint32_t addr) {
    asm volatile("ldmatrix.sync.aligned.m8n8.x2.shared.b16 {%0,%1}, [%2];"
                 : "=r"(r0), "=r"(r1) : "r"(addr));
}
__device__ __forceinline__ void mma_f16(float (&c)[4], const uint32_t (&a)[4],
                                        uint32_t b0, uint32_t b1) {
    asm volatile(
        "mma.sync.aligned.m16n8k16.row.col.f32.f16.f16.f32 "
        "{%0,%1,%2,%3}, {%4,%5,%6,%7}, {%8,%9}, {%0,%1,%2,%3};"
        : "+f"(c[0]), "+f"(c[1]), "+f"(c[2]), "+f"(c[3])
        : "r"(a[0]), "r"(a[1]), "r"(a[2]), "r"(a[3]), "r"(b0), "r"(b1));
}
__device__ __forceinline__ uint32_t packh(__half a, __half b) {
    __half2 h; h.x = a; h.y = b;
    return *(uint32_t*)&h;
}
__device__ __forceinline__ float silu_f(float h) {
    return __fdividef(h, 1.f + __expf(-h));
}

// ---------------- stage 1: per-sample partial sums --------------------------
__global__ void cp_stats_kernel(const float* __restrict__ z0) {
    const int b = blockIdx.y;
    const float4* z4 = (const float4*)(z0 + (size_t)b * CHW);
    const int n4 = CHW / 4;
    float s = 0.f, q = 0.f;
    for (int i = blockIdx.x * RED_THREADS + threadIdx.x; i < n4;
         i += RED_BLOCKS * RED_THREADS) {
        float4 v = z4[i];
        s += (v.x + v.y) + (v.z + v.w);
        q += (v.x * v.x + v.y * v.y) + (v.z * v.z + v.w * v.w);
    }
    #pragma unroll
    for (int off = 16; off; off >>= 1) {
        s += __shfl_down_sync(0xffffffffu, s, off);
        q += __shfl_down_sync(0xffffffffu, q, off);
    }
    __shared__ float ss[RED_THREADS / 32], sq[RED_THREADS / 32];
    const int w = threadIdx.x >> 5;
    if ((threadIdx.x & 31) == 0) { ss[w] = s; sq[w] = q; }
    __syncthreads();
    if (threadIdx.x == 0) {
        float S = 0.f, Q = 0.f;
        #pragma unroll
        for (int i = 0; i < RED_THREADS / 32; i++) { S += ss[i]; Q += sq[i]; }
        g_psum[b * RED_BLOCKS + blockIdx.x] = S;
        g_psq [b * RED_BLOCKS + blockIdx.x] = Q;
    }
}

// ---------------- stage 2: finalize + fp16 weights --------------------------
__global__ void cp_finalize_kernel(const float* __restrict__ w1,
                                   const float* __restrict__ w2) {
    const int t = threadIdx.x;   // 256
    if (t < NSAMP) {
        float S = 0.f, Q = 0.f;
        for (int i = 0; i < RED_BLOCKS; i++) {
            S += g_psum[t * RED_BLOCKS + i];
            Q += g_psq [t * RED_BLOCKS + i];
        }
        const float inv_n = 1.f / (float)CHW;
        const float mu  = S * inv_n;
        const float var = Q * inv_n - mu * mu;
        g_mu[t] = mu;
        g_rs[t] = rsqrtf(var + 1e-5f);
    }
    __half* w1h = (__half*)g_w1h;
    __half* w2h = (__half*)g_w2h;
    for (int i = t; i < 128 * 64; i += 256) {      // w1[h][k] -> [h][72]
        const int h = i >> 6, k = i & 63;
        w1h[h * 72 + k] = __float2half_rn(w1[h * 64 + k]);
    }
    for (int i = t; i < 64 * 128; i += 256) {      // w2[o][h] -> [o][136]
        const int o = i >> 7, h = i & 127;
        w2h[o * 136 + h] = __float2half_rn(w2[o * 128 + h]);
    }
}

// z2 pipeline macros (j must be a compile-time-foldable expression)
#define Z2_PRE(slot, j) do {                                                    \
    const int _i = tid + (j) * 256;                                             \
    const int _c = _i >> 5, _f = (_i & 31) * 4;                                 \
    zvp[slot] = *(const float4*)(zb + (size_t)(CC + _c) * HW + p0 + _f);        \
    if ((j) >= 4)                                                               \
        rvp[slot] = *(const float4*)(zb + (size_t)(2 * _c + 1) * HW + p0 + _f); \
} while (0)

#define Z2_FIN(slot, j) do {                                                    \
    const int _i = tid + (j) * 256;                                             \
    const int _c = _i >> 5, _f = (_i & 31) * 4;                                 \
    const float4 _zv = zvp[slot];                                               \
    const float4 _rv = ((j) < 4)                                                \
        ? *(const float4*)(stg + (2 * _c + 1) * STG_STR + _f) : rvp[slot];      \
    float4 _ov;                                                                 \
    _ov.x = (_zv.x - mu) * rs + _rv.x; _ov.y = (_zv.y - mu) * rs + _rv.y;       \
    _ov.z = (_zv.z - mu) * rs + _rv.z; _ov.w = (_zv.w - mu) * rs + _rv.w;       \
    *(float4*)(ob + (size_t)(2 * _c + 1) * HW + p0 + _f) = _ov;                 \
} while (0)

// ---------------- stage 3: HMMA main kernel (2 CTAs/SM) ---------------------
__global__ void __launch_bounds__(256, 2)
cp_main_kernel(const float* __restrict__ z0,
               const float* __restrict__ b1,
               const float* __restrict__ b2,
               float* __restrict__ out) {
    extern __shared__ char smc[];
    const uint32_t sb = smem_u32(smc);
    const int tid = threadIdx.x;
    const int w = tid >> 5, lane = tid & 31;
    const int g = lane >> 2, tig = lane & 3;
    const int lrow = lane & 15, lk = lane >> 4;          // ldsm.x4 mapping
    const int brow = lane & 7,  bk = (lane >> 3) & 1;    // ldsm.x2 mapping

    const int b = blockIdx.x / BLOCKS_PER_SAMPLE;
    const float* zb = z0 + (size_t)b * CHW;
    float*       ob = out + (size_t)b * CHW;
    const int p_base = (blockIdx.x % BLOCKS_PER_SAMPLE) * (TPB * 128);
    float* stg = (float*)(smc + OFF_STG);
    float* Y   = (float*)(smc + OFF_A);

    // ---- prologue: stage z1 tile 0 + weights + biases ----
    #pragma unroll
    for (int k = 0; k < 8; k++) {
        const int i = tid + k * 256;
        const int c = i >> 5, f = (i & 31) * 4;
        *(float4*)(stg + c * STG_STR + f) = *(const float4*)(zb + (size_t)c * HW + p_base + f);
    }
    for (int i = tid; i < 1152; i += 256) ((uint4*)(smc + OFF_W1))[i] = g_w1h[i];
    for (int i = tid; i < 1088; i += 256) ((uint4*)(smc + OFF_W2))[i] = g_w2h[i];
    float* b1s = (float*)(smc + OFF_B1);
    float* b2s = (float*)(smc + OFF_B2);
    if (tid < 128) b1s[tid] = b1[tid];
    if (tid < 64)  b2s[tid] = b2[tid];

    const float mu = g_mu[b];
    const float rs = g_rs[b];

    for (int tl = 0; tl < TPB; tl++) {
        const int p0 = p_base + tl * 128;
        __syncthreads();   // stg(tl) visible; Y reads of tl-1 done

        // ---- convert: normalize -> A fp16 [px][72] ----
        #pragma unroll
        for (int k = 0; k < 4; k++) {
            const int i = tid + k * 256;          // 128px x 8 c-groups
            const int px = i & 127, c0 = (i >> 7) * 8;
            uint32_t hw[4];
            #pragma unroll
            for (int j = 0; j < 4; j++) {
                const float v0 = (stg[(c0 + 2 * j)     * STG_STR + px] - mu) * rs;
                const float v1 = (stg[(c0 + 2 * j + 1) * STG_STR + px] - mu) * rs;
                hw[j] = packh(__float2half_rn(v0), __float2half_rn(v1));
            }
            *(uint4*)(smc + OFF_A + px * 144 + c0 * 2) = make_uint4(hw[0], hw[1], hw[2], hw[3]);
        }
        __syncthreads();   // A ready; stg still readable

        // ---- GEMM1 [16px x 128h], K=64, with z2 stream interleaved ----
        float acc[16][4];
        #pragma unroll
        for (int nt = 0; nt < 16; nt++)
            #pragma unroll
            for (int i = 0; i < 4; i++) acc[nt][i] = 0.f;

        float4 zvp[2], rvp[2];
        Z2_PRE(0, 0);
        Z2_PRE(1, 1);
        #pragma unroll
        for (int ks = 0; ks < 4; ks++) {
            uint32_t aF[4];
            ldsm_x4(aF, sb + OFF_A + (w * 16 + lrow) * 144 + (ks * 16 + lk * 8) * 2);
            #pragma unroll
            for (int nt = 0; nt < 8; nt++) {
                const uint32_t bd = sb + OFF_W1 + (nt * 8 + brow) * 144
                                  + (ks * 16 + bk * 8) * 2;
                uint32_t b0, b1r;
                ldsm_x2(b0, b1r, bd);
                mma_f16(acc[nt], aF, b0, b1r);
            }
            Z2_FIN(0, 2 * ks);
            if (2 * ks + 2 < 8) Z2_PRE(0, 2 * ks + 2);
            #pragma unroll
            for (int nt = 8; nt < 16; nt++) {
                const uint32_t bd = sb + OFF_W1 + (nt * 8 + brow) * 144
                                  + (ks * 16 + bk * 8) * 2;
                uint32_t b0, b1r;
                ldsm_x2(b0, b1r, bd);
                mma_f16(acc[nt], aF, b0, b1r);
            }
            Z2_FIN(1, 2 * ks + 1);
            if (2 * ks + 3 < 8) Z2_PRE(1, 2 * ks + 3);
        }

        // ---- SiLU(+b1) -> fp16 frags in registers (C-frag == next A-frag) --
        uint32_t sh[16][2];
        #pragma unroll
        for (int nt = 0; nt < 16; nt++) {
            const int h0 = nt * 8 + 2 * tig;
            const float bi0 = b1s[h0], bi1 = b1s[h0 + 1];
            sh[nt][0] = packh(__float2half_rn(silu_f(acc[nt][0] + bi0)),
                              __float2half_rn(silu_f(acc[nt][1] + bi1)));
            sh[nt][1] = packh(__float2half_rn(silu_f(acc[nt][2] + bi0)),
                              __float2half_rn(silu_f(acc[nt][3] + bi1)));
        }
        __syncthreads();   // all A reads done -> Y (A union) free; stg dead

        // ---- GEMM2: [16px x 64o] per warp, K=128, A from registers ----
        float acc2[8][4];
        #pragma unroll
        for (int nt = 0; nt < 8; nt++)
            #pragma unroll
            for (int i = 0; i < 4; i++) acc2[nt][i] = 0.f;
        #pragma unroll
        for (int ks = 0; ks < 8; ks++) {
            const uint32_t aF[4] = { sh[2 * ks][0], sh[2 * ks][1],
                                     sh[2 * ks + 1][0], sh[2 * ks + 1][1] };
            #pragma unroll
            for (int nt = 0; nt < 8; nt++) {
                const uint32_t bd = sb + OFF_W2 + (nt * 8 + brow) * 272
                                  + (ks * 16 + bk * 8) * 2;
                uint32_t b0, b1r;
                ldsm_x2(b0, b1r, bd);
                mma_f16(acc2[nt], aF, b0, b1r);
            }
        }
        // ---- stash y+b2 into Y [o][132] (conflict-free) ----
        const int pxl = w * 16 + g;
        #pragma unroll
        for (int nt = 0; nt < 8; nt++) {
            const int o0 = nt * 8 + 2 * tig;
            Y[o0 * 132 + pxl]           = acc2[nt][0] + b2s[o0];
            Y[(o0 + 1) * 132 + pxl]     = acc2[nt][1] + b2s[o0 + 1];
            Y[o0 * 132 + pxl + 8]       = acc2[nt][2] + b2s[o0];
            Y[(o0 + 1) * 132 + pxl + 8] = acc2[nt][3] + b2s[o0 + 1];
        }
        __syncthreads();   // Y visible; stg free for next tile

        // ---- next tile's z1 staging (overlaps write-out) ----
        if (tl + 1 < TPB) {
            const int pn = p_base + (tl + 1) * 128;
            #pragma unroll
            for (int k = 0; k < 8; k++) {
                const int i = tid + k * 256;
                const int c = i >> 5, f = (i & 31) * 4;
                *(float4*)(stg + c * STG_STR + f) =
                    *(const float4*)(zb + (size_t)c * HW + pn + f);
            }
        }
        // ---- write-out: out[2o] = Y + z0[2o] (residuals are L2 hits) ----
        #pragma unroll
        for (int k = 0; k < 8; k++) {
            const int i = tid + k * 256;          // 64o x 32 float4
            const int o = i >> 5, f = (i & 31) * 4;
            const float4 yv = *(const float4*)(Y + o * 132 + f);
            const float4 rv = *(const float4*)(zb + (size_t)(2 * o) * HW + p0 + f);
            float4 ov;
            ov.x = yv.x + rv.x; ov.y = yv.y + rv.y;
            ov.z = yv.z + rv.z; ov.w = yv.w + rv.w;
            *(float4*)(ob + (size_t)(2 * o) * HW + p0 + f) = ov;
        }
    }
}

// ---------------------------------------------------------------------------
extern "C" void kernel_launch(void* const* d_in, const int* in_sizes, int n_in,
                              void* d_out, int out_size) {
    const float* z0 = (const float*)d_in[0];
    const float* w1 = (const float*)d_in[1];
    const float* b1 = (const float*)d_in[2];
    const float* w2 = (const float*)d_in[3];
    const float* b2 = (const float*)d_in[4];
    float* out = (float*)d_out;

    static bool attr_set = false;
    if (!attr_set) {
        cudaFuncSetAttribute(cp_main_kernel,
                             cudaFuncAttributeMaxDynamicSharedMemorySize,
                             SMEM_MAIN);
        attr_set = true;
    }

    cp_stats_kernel<<<dim3(RED_BLOCKS, NSAMP), RED_THREADS>>>(z0);
    cp_finalize_kernel<<<1, 256>>>(w1, w2);
    cp_main_kernel<<<MAIN_GRID, 256, SMEM_MAIN>>>(z0, b1, b2, out);
}